// round 2
// baseline (speedup 1.0000x reference)
#include <cuda_runtime.h>
#include <cstdint>
#include <cstddef>

// ============================================================================
// TriLinear: out[b,q,k] = (Q.w1)[b,q] + (K.w2)[b,k] + sum_d Q[b,q,d]*w3[d]*K[b,k,d]
// B=32, L=1024, D=768, fp32.
//
// Base-ISA build (compute_103 PTX -> no tcgen05). Tensor path = mma.sync tf32
// (m16n8k8, sm_80 base feature, runs on legacy HMMA pipe on sm_103a).
// Batched GEMM Q @ diag(w3) @ K^T, bias terms precomputed + epilogue-folded.
// ============================================================================

#define Bsz   32
#define Lseq  1024
#define Dd    768

#define BM    128
#define BN    128
#define BK    32
#define NIT   (Dd / BK)      // 24

#define PAD   36             // floats per smem row (32 data + 4 pad, 144B: 16B-aligned)
#define TILEF (128 * PAD)    // 4608 floats per tile

// dynamic smem layout (float offsets): A0 B0 A1 B1 qlog[128] klog[128]
#define OFF_A(s)  ((s) * 2 * TILEF)
#define OFF_B(s)  ((s) * 2 * TILEF + TILEF)
#define OFF_QL    (4 * TILEF)
#define OFF_KL    (4 * TILEF + 128)
#define SMEM_BYTES ((4 * TILEF + 256) * 4)   // 74752 B

// ---------------------------------------------------------------------------
__device__ __forceinline__ uint32_t f2tf32(float x) {
    uint32_t r;
    asm("cvt.rna.tf32.f32 %0, %1;" : "=r"(r) : "f"(x));
    return r;
}

__device__ __forceinline__ void mma_tf32(float* d,
                                         uint32_t a0, uint32_t a1, uint32_t a2, uint32_t a3,
                                         uint32_t b0, uint32_t b1) {
    asm volatile(
        "mma.sync.aligned.m16n8k8.row.col.f32.tf32.tf32.f32 "
        "{%0,%1,%2,%3}, {%4,%5,%6,%7}, {%8,%9}, {%0,%1,%2,%3};"
        : "+f"(d[0]), "+f"(d[1]), "+f"(d[2]), "+f"(d[3])
        : "r"(a0), "r"(a1), "r"(a2), "r"(a3), "r"(b0), "r"(b1));
}

// ---------------------------------------------------------------------------
// Bias scratch
// ---------------------------------------------------------------------------
__device__ float g_qlog[Bsz * Lseq];
__device__ float g_klog[Bsz * Lseq];

__device__ __forceinline__ void rowdot_body(const float4* __restrict__ X,
                                            const float4* __restrict__ W,
                                            float* __restrict__ out) {
    int warp = (blockIdx.x * blockDim.x + threadIdx.x) >> 5;
    int lane = threadIdx.x & 31;
    const float4* xr = X + (size_t)warp * (Dd / 4);
    float s = 0.f;
    #pragma unroll
    for (int i = 0; i < 6; ++i) {
        int idx = lane + i * 32;
        float4 a = xr[idx];
        float4 b = W[idx];
        s += a.x * b.x + a.y * b.y + a.z * b.z + a.w * b.w;
    }
    #pragma unroll
    for (int o = 16; o; o >>= 1) s += __shfl_xor_sync(0xFFFFFFFFu, s, o);
    if (lane == 0) out[warp] = s;
}

__global__ void __launch_bounds__(256) rowdot_q_kernel(const float4* __restrict__ X,
                                                       const float4* __restrict__ W) {
    rowdot_body(X, W, g_qlog);
}
__global__ void __launch_bounds__(256) rowdot_k_kernel(const float4* __restrict__ X,
                                                       const float4* __restrict__ W) {
    rowdot_body(X, W, g_klog);
}

// ---------------------------------------------------------------------------
// Main GEMM: 256 threads, 8 warps = 2(M) x 4(N), warp tile 64x32.
// ---------------------------------------------------------------------------
__global__ void __launch_bounds__(256, 1)
trilinear_gemm_kernel(const float* __restrict__ Q, const float* __restrict__ K,
                      const float* __restrict__ w3, float* __restrict__ out) {
    extern __shared__ float smem[];

    const int tid  = threadIdx.x;
    const int lane = tid & 31;
    const int warp = tid >> 5;
    const int wm   = warp >> 2;        // 0..1 : M position (64 rows)
    const int wn   = warp & 3;         // 0..3 : N position (32 cols)

    const int b     = blockIdx.z;
    const int mBase = blockIdx.y * BM;
    const int nBase = blockIdx.x * BN;

    // ---- load thread mapping: row = tid>>1 (0..127), 64B column half ----
    const int lrow = tid >> 1;
    const int cb4  = (tid & 1) * 4;    // float4-quad index within 32-float row

    const float* Ag = Q + ((size_t)b * Lseq + mBase + lrow) * Dd;
    const float* Bg = K + ((size_t)b * Lseq + nBase + lrow) * Dd;

    // stage bias tiles into smem
    if (tid < 128) {
        smem[OFF_QL + tid] = g_qlog[(size_t)b * Lseq + mBase + tid];
        smem[OFF_KL + tid] = g_klog[(size_t)b * Lseq + nBase + tid];
    }

    float acc[4][4][4];
    #pragma unroll
    for (int i = 0; i < 4; ++i)
        #pragma unroll
        for (int j = 0; j < 4; ++j)
            #pragma unroll
            for (int c = 0; c < 4; ++c) acc[i][j][c] = 0.f;

    float4 ra[4], rb[4];

    // ---- prologue: load k-chunk 0 ----
    {
        const int kOff = 0;
        #pragma unroll
        for (int j = 0; j < 4; ++j) {
            ra[j] = *(const float4*)(Ag + kOff + (cb4 + j) * 4);
            float4 v = *(const float4*)(Bg + kOff + (cb4 + j) * 4);
            float4 w = *(const float4*)(w3 + kOff + (cb4 + j) * 4);
            rb[j] = make_float4(v.x * w.x, v.y * w.y, v.z * w.z, v.w * w.w);
        }
    }

    for (int it = 0; it < NIT; ++it) {
        const int s = it & 1;
        float* As = smem + OFF_A(s);
        float* Bs = smem + OFF_B(s);

        // ---- store current regs to stage s (tf32 RN rounding here) ----
        #pragma unroll
        for (int j = 0; j < 4; ++j) {
            uint4 ta, tb;
            ta.x = f2tf32(ra[j].x); ta.y = f2tf32(ra[j].y);
            ta.z = f2tf32(ra[j].z); ta.w = f2tf32(ra[j].w);
            tb.x = f2tf32(rb[j].x); tb.y = f2tf32(rb[j].y);
            tb.z = f2tf32(rb[j].z); tb.w = f2tf32(rb[j].w);
            *(uint4*)(As + lrow * PAD + (cb4 + j) * 4) = ta;
            *(uint4*)(Bs + lrow * PAD + (cb4 + j) * 4) = tb;
        }
        __syncthreads();

        // ---- issue next chunk's LDGs (latency hidden by MMAs below) ----
        if (it + 1 < NIT) {
            const int kOff = (it + 1) * BK;
            #pragma unroll
            for (int j = 0; j < 4; ++j) {
                ra[j] = *(const float4*)(Ag + kOff + (cb4 + j) * 4);
                float4 v = *(const float4*)(Bg + kOff + (cb4 + j) * 4);
                float4 w = *(const float4*)(w3 + kOff + (cb4 + j) * 4);
                rb[j] = make_float4(v.x * w.x, v.y * w.y, v.z * w.z, v.w * w.w);
            }
        }

        // ---- MMA over stage s: 4 k-steps of 8 ----
        const uint32_t* Au = (const uint32_t*)As;
        const uint32_t* Bu = (const uint32_t*)Bs;
        #pragma unroll
        for (int ks = 0; ks < 4; ++ks) {
            const int c0 = ks * 8 + (lane & 3);
            uint32_t afr[4][4];
            #pragma unroll
            for (int i = 0; i < 4; ++i) {
                const int r0 = wm * 64 + i * 16 + (lane >> 2);
                afr[i][0] = Au[r0 * PAD + c0];
                afr[i][1] = Au[(r0 + 8) * PAD + c0];
                afr[i][2] = Au[r0 * PAD + c0 + 4];
                afr[i][3] = Au[(r0 + 8) * PAD + c0 + 4];
            }
            #pragma unroll
            for (int jn = 0; jn < 4; ++jn) {
                const int n0 = wn * 32 + jn * 8 + (lane >> 2);
                const uint32_t b0 = Bu[n0 * PAD + c0];
                const uint32_t b1 = Bu[n0 * PAD + c0 + 4];
                #pragma unroll
                for (int i = 0; i < 4; ++i)
                    mma_tf32(acc[i][jn], afr[i][0], afr[i][1], afr[i][2], afr[i][3], b0, b1);
            }
        }
        __syncthreads();
    }

    // ---- epilogue: add qlog/klog, store ----
    const float* ql = smem + OFF_QL;
    const float* kl = smem + OFF_KL;
    #pragma unroll
    for (int i = 0; i < 4; ++i) {
        const int lr0 = wm * 64 + i * 16 + (lane >> 2);
        const float qv0 = ql[lr0];
        const float qv1 = ql[lr0 + 8];
        float* d0 = out + ((size_t)b * Lseq + mBase + lr0) * Lseq + nBase;
        float* d1 = d0 + 8 * Lseq;
        #pragma unroll
        for (int jn = 0; jn < 4; ++jn) {
            const int lc = wn * 32 + jn * 8 + 2 * (lane & 3);
            const float k0 = kl[lc], k1 = kl[lc + 1];
            float2 o0 = make_float2(acc[i][jn][0] + qv0 + k0,
                                    acc[i][jn][1] + qv0 + k1);
            float2 o1 = make_float2(acc[i][jn][2] + qv1 + k0,
                                    acc[i][jn][3] + qv1 + k1);
            *(float2*)(d0 + lc) = o0;
            *(float2*)(d1 + lc) = o1;
        }
    }
}

// ---------------------------------------------------------------------------
// Launch
// ---------------------------------------------------------------------------
extern "C" void kernel_launch(void* const* d_in, const int* in_sizes, int n_in,
                              void* d_out, int out_size) {
    const float* q  = (const float*)d_in[0];
    const float* k  = (const float*)d_in[1];
    const float* w1 = (const float*)d_in[2];
    const float* w2 = (const float*)d_in[3];
    const float* w3 = (const float*)d_in[4];
    float* out = (float*)d_out;

    // Prepass: bias logits (one warp per row)
    const int rd_blocks = (Bsz * Lseq) / 8;
    rowdot_q_kernel<<<rd_blocks, 256>>>((const float4*)q, (const float4*)w1);
    rowdot_k_kernel<<<rd_blocks, 256>>>((const float4*)k, (const float4*)w2);

    // Main batched GEMM
    static bool attr_set = false;
    if (!attr_set) {
        cudaFuncSetAttribute(trilinear_gemm_kernel,
                             cudaFuncAttributeMaxDynamicSharedMemorySize, SMEM_BYTES);
        attr_set = true;
    }
    dim3 grid(Lseq / BN, Lseq / BM, Bsz);   // (8, 8, 32)
    trilinear_gemm_kernel<<<grid, 256, SMEM_BYTES>>>(q, k, w3, out);
}

// round 16
// speedup vs baseline: 1.3706x; 1.3706x over previous
#include <cuda_runtime.h>
#include <cstdint>
#include <cstddef>

// ============================================================================
// TriLinear: out[b,q,k] = (Q.w1)[b,q] + (K.w2)[b,k] + sum_d Q[b,q,d]*w3[d]*K[b,k,d]
// B=32, L=1024, D=768, fp32.
//
// Single fused kernel. Base-ISA mma.sync tf32 (m16n8k8) batched GEMM
// Q @ diag(w3) @ K^T with warp-specialized 3-stage SMEM pipeline.
//   - 8 consumer warps: 2(M) x 4(N) grid of 64x64 warp tiles -> CTA 128x256
//   - 2 producer warps: coalesced LDG (4 full 128B lines / instr) -> RN-round
//     to tf32 (+ w3 fold on K side) -> conflict-free STS. Bias dots q.w1 / k.w2
//     accumulated in-flight from the same registers (no prepass kernels).
// (Resubmission: R3-R15 benches were broker GPUAcquisitionTimeouts —
//  this kernel has never executed; keeping it bit-identical for attribution.)
// ============================================================================

#define Bsz   32
#define Lseq  1024
#define Dd    768

#define BM    128
#define BN    256
#define BK    32
#define NIT   (Dd / BK)     // 24
#define NSTG  3

#define NTHREADS 320        // 8 consumer warps + 2 producer warps
#define NCONS    256

#define PAD    36           // floats per smem tile row (32 data + 4 pad)
#define STGF   ((BM + BN) * PAD)          // 13824 floats per stage
#define OFF_A(s)  ((s) * STGF)
#define OFF_B(s)  ((s) * STGF + BM * PAD)
#define OFF_QL    (NSTG * STGF)           // 41472
#define OFF_KL    (OFF_QL + BM)           // +128
#define OFF_W1    (OFF_KL + BN)           // +256
#define OFF_W2    (OFF_W1 + Dd)
#define OFF_W3    (OFF_W2 + Dd)
#define SMEM_FLOATS (OFF_W3 + Dd)
#define SMEM_BYTES  (SMEM_FLOATS * 4)     // 176640

// named barriers: full[s] = 1+s, empty[s] = 4+s
#define BAR_SYNC(id)   asm volatile("bar.sync %0, %1;"   :: "r"(id), "r"(NTHREADS) : "memory")
#define BAR_ARRIVE(id) asm volatile("bar.arrive %0, %1;" :: "r"(id), "r"(NTHREADS) : "memory")
#define MEMBAR_CTA()   asm volatile("membar.cta;" ::: "memory")

// ---------------------------------------------------------------------------
__device__ __forceinline__ uint32_t f2tf32(float x) {
    uint32_t r;
    asm("cvt.rna.tf32.f32 %0, %1;" : "=r"(r) : "f"(x));
    return r;
}

__device__ __forceinline__ void mma_tf32(float* d,
                                         uint32_t a0, uint32_t a1, uint32_t a2, uint32_t a3,
                                         uint32_t b0, uint32_t b1) {
    asm volatile(
        "mma.sync.aligned.m16n8k8.row.col.f32.tf32.tf32.f32 "
        "{%0,%1,%2,%3}, {%4,%5,%6,%7}, {%8,%9}, {%0,%1,%2,%3};"
        : "+f"(d[0]), "+f"(d[1]), "+f"(d[2]), "+f"(d[3])
        : "r"(a0), "r"(a1), "r"(a2), "r"(a3), "r"(b0), "r"(b1));
}

__device__ __forceinline__ float dot4(float4 a, float4 b) {
    return a.x * b.x + a.y * b.y + a.z * b.z + a.w * b.w;
}

// ---------------------------------------------------------------------------
__global__ void __launch_bounds__(NTHREADS, 1)
trilinear_kernel(const float* __restrict__ Q, const float* __restrict__ K,
                 const float* __restrict__ w1, const float* __restrict__ w2,
                 const float* __restrict__ w3, float* __restrict__ out) {
    extern __shared__ float smem[];

    const int tid  = threadIdx.x;
    const int lane = tid & 31;
    const int warp = tid >> 5;

    const int b     = blockIdx.z;
    const int mBase = blockIdx.y * BM;
    const int nBase = blockIdx.x * BN;

    // stage w1/w2/w3 (each 768 floats = 192 float4)
    if (tid < 192) {
        ((float4*)(smem + OFF_W1))[tid] = ((const float4*)w1)[tid];
        ((float4*)(smem + OFF_W2))[tid] = ((const float4*)w2)[tid];
        ((float4*)(smem + OFF_W3))[tid] = ((const float4*)w3)[tid];
    }
    __syncthreads();

    if (warp >= 8) {
        // ==================== PRODUCERS (warps 8,9 = 64 threads) ===========
        const int pw = warp - 8;       // 0..1
        const int rg = lane >> 3;      // 0..3  row within 4-row quad
        const int pc = lane & 7;       // 0..7  16B column chunk

        // thread's base rows: A slot sa: row = sa*8 + pw*4 + rg  (sa 0..15)
        //                     B slot sb: row = sb*8 + pw*4 + rg  (sb 0..31)
        const int rbase = pw * 4 + rg;
        const float* Ag = Q + ((size_t)b * Lseq + mBase + rbase) * Dd + pc * 4;
        const float* Bg = K + ((size_t)b * Lseq + nBase + rbase) * Dd + pc * 4;

        float qacc[16], kacc[32];
        #pragma unroll
        for (int i = 0; i < 16; ++i) qacc[i] = 0.f;
        #pragma unroll
        for (int i = 0; i < 32; ++i) kacc[i] = 0.f;

        int s = 0;
        for (int it = 0; it < NIT; ++it) {
            if (it >= NSTG) BAR_SYNC(4 + s);

            const int kOff = it * BK;
            const float4 w1v = ((const float4*)(smem + OFF_W1 + kOff))[pc];
            const float4 w2v = ((const float4*)(smem + OFF_W2 + kOff))[pc];
            const float4 w3v = ((const float4*)(smem + OFF_W3 + kOff))[pc];
            float* As = smem + OFF_A(s);
            float* Bs = smem + OFF_B(s);

            #pragma unroll
            for (int sa = 0; sa < 16; ++sa) {
                const int row = sa * 8 + rbase;
                float4 v = *(const float4*)(Ag + (size_t)sa * 8 * Dd + kOff);
                qacc[sa] += dot4(v, w1v);
                uint4 t;
                t.x = f2tf32(v.x); t.y = f2tf32(v.y);
                t.z = f2tf32(v.z); t.w = f2tf32(v.w);
                *(uint4*)(As + row * PAD + pc * 4) = t;
            }
            #pragma unroll
            for (int sb = 0; sb < 32; ++sb) {
                const int row = sb * 8 + rbase;
                float4 v = *(const float4*)(Bg + (size_t)sb * 8 * Dd + kOff);
                kacc[sb] += dot4(v, w2v);
                uint4 t;
                t.x = f2tf32(v.x * w3v.x); t.y = f2tf32(v.y * w3v.y);
                t.z = f2tf32(v.z * w3v.z); t.w = f2tf32(v.w * w3v.w);
                *(uint4*)(Bs + row * PAD + pc * 4) = t;
            }
            MEMBAR_CTA();
            BAR_ARRIVE(1 + s);
            if (++s == NSTG) s = 0;
        }

        // bias reduce: 8 lanes per row (xor over pc bits)
        #pragma unroll
        for (int sa = 0; sa < 16; ++sa) {
            float v = qacc[sa];
            v += __shfl_xor_sync(0xFFFFFFFFu, v, 1);
            v += __shfl_xor_sync(0xFFFFFFFFu, v, 2);
            v += __shfl_xor_sync(0xFFFFFFFFu, v, 4);
            if (pc == 0) smem[OFF_QL + sa * 8 + rbase] = v;
        }
        #pragma unroll
        for (int sb = 0; sb < 32; ++sb) {
            float v = kacc[sb];
            v += __shfl_xor_sync(0xFFFFFFFFu, v, 1);
            v += __shfl_xor_sync(0xFFFFFFFFu, v, 2);
            v += __shfl_xor_sync(0xFFFFFFFFu, v, 4);
            if (pc == 0) smem[OFF_KL + sb * 8 + rbase] = v;
        }
        __syncthreads();   // match consumers' pre-epilogue barrier
    } else {
        // ==================== CONSUMERS (warps 0..7) ========================
        const int wm = warp >> 2;      // 0..1 : 64-row slab
        const int wn = warp & 3;       // 0..3 : 64-col slab
        const int g  = lane >> 2;      // 0..7
        const int t  = lane & 3;       // 0..3

        float acc[4][8][4];
        #pragma unroll
        for (int i = 0; i < 4; ++i)
            #pragma unroll
            for (int j = 0; j < 8; ++j)
                #pragma unroll
                for (int c = 0; c < 4; ++c) acc[i][j][c] = 0.f;

        int s = 0;
        for (int it = 0; it < NIT; ++it) {
            BAR_SYNC(1 + s);
            const uint32_t* Au = (const uint32_t*)(smem + OFF_A(s));
            const uint32_t* Bu = (const uint32_t*)(smem + OFF_B(s));

            #pragma unroll
            for (int ks = 0; ks < 4; ++ks) {
                const int c0 = ks * 8 + t;
                uint32_t af[4][4];
                #pragma unroll
                for (int i = 0; i < 4; ++i) {
                    const int r0 = wm * 64 + i * 16 + g;
                    af[i][0] = Au[r0 * PAD + c0];
                    af[i][1] = Au[(r0 + 8) * PAD + c0];
                    af[i][2] = Au[r0 * PAD + c0 + 4];
                    af[i][3] = Au[(r0 + 8) * PAD + c0 + 4];
                }
                #pragma unroll
                for (int jn = 0; jn < 8; ++jn) {
                    const int n0 = wn * 64 + jn * 8 + g;
                    const uint32_t b0 = Bu[n0 * PAD + c0];
                    const uint32_t b1 = Bu[n0 * PAD + c0 + 4];
                    #pragma unroll
                    for (int i = 0; i < 4; ++i)
                        mma_tf32(acc[i][jn], af[i][0], af[i][1], af[i][2], af[i][3], b0, b1);
                }
            }
            BAR_ARRIVE(4 + s);
            if (++s == NSTG) s = 0;
        }

        __syncthreads();   // wait for producers' qlog/klog

        // ---- epilogue ----
        const float* ql = smem + OFF_QL;
        const float* kl = smem + OFF_KL;
        #pragma unroll
        for (int i = 0; i < 4; ++i) {
            const int r0  = wm * 64 + i * 16 + g;
            const float qv0 = ql[r0];
            const float qv1 = ql[r0 + 8];
            float* d0 = out + ((size_t)b * Lseq + mBase + r0) * Lseq + nBase + wn * 64;
            float* d1 = d0 + 8 * Lseq;
            #pragma unroll
            for (int jn = 0; jn < 8; ++jn) {
                const int lc = jn * 8 + 2 * t;
                const float k0 = kl[wn * 64 + lc];
                const float k1 = kl[wn * 64 + lc + 1];
                *(float2*)(d0 + lc) = make_float2(acc[i][jn][0] + qv0 + k0,
                                                  acc[i][jn][1] + qv0 + k1);
                *(float2*)(d1 + lc) = make_float2(acc[i][jn][2] + qv1 + k0,
                                                  acc[i][jn][3] + qv1 + k1);
            }
        }
    }
}

// ---------------------------------------------------------------------------
extern "C" void kernel_launch(void* const* d_in, const int* in_sizes, int n_in,
                              void* d_out, int out_size) {
    const float* q  = (const float*)d_in[0];
    const float* k  = (const float*)d_in[1];
    const float* w1 = (const float*)d_in[2];
    const float* w2 = (const float*)d_in[3];
    const float* w3 = (const float*)d_in[4];
    float* out = (float*)d_out;

    cudaFuncSetAttribute(trilinear_kernel,
                         cudaFuncAttributeMaxDynamicSharedMemorySize, SMEM_BYTES);
    dim3 grid(Lseq / BN, Lseq / BM, Bsz);   // (4, 8, 32)
    trilinear_kernel<<<grid, NTHREADS, SMEM_BYTES>>>(q, k, w1, w2, w3, out);
}